// round 2
// baseline (speedup 1.0000x reference)
#include <cuda_runtime.h>
#include <math.h>

#define NSEQ 64
static constexpr int LA = 2305;   // run0 seq length (1 gt + 48*48)
static constexpr int LB = 3073;   // run1/2 seq length (1 gt + 128*24)

// ---------- scratch (device globals; allocation-free) ----------
__device__ float gA_xz[NSEQ*LA*128];
__device__ float gA_xs[NSEQ*LA*64];
__device__ float gA_dt[NSEQ*LA*64];
__device__ float gA_bc[NSEQ*LA*32];
__device__ float gA_y [NSEQ*(LA-1)*64];
__device__ float gA_o [NSEQ*(LA-1)*32];

__device__ float gB_xz0[NSEQ*LB*96];
__device__ float gB_xs0[NSEQ*LB*48];
__device__ float gB_dt0[NSEQ*LB*48];
__device__ float gB_bc0[NSEQ*LB*32];
__device__ float gB_y0 [NSEQ*(LB-1)*48];
__device__ float gB_o0 [NSEQ*(LB-1)*24];

__device__ float gB_xz1[NSEQ*LB*96];
__device__ float gB_xs1[NSEQ*LB*48];
__device__ float gB_dt1[NSEQ*LB*48];
__device__ float gB_bc1[NSEQ*LB*32];
__device__ float gB_y1 [NSEQ*(LB-1)*48];
__device__ float gB_o1 [NSEQ*(LB-1)*24];

template<int RUN> __device__ __forceinline__ float* bufXZ(){
  if constexpr (RUN==0) return gA_xz; else if constexpr (RUN==1) return gB_xz0; else return gB_xz1; }
template<int RUN> __device__ __forceinline__ float* bufXS(){
  if constexpr (RUN==0) return gA_xs; else if constexpr (RUN==1) return gB_xs0; else return gB_xs1; }
template<int RUN> __device__ __forceinline__ float* bufDT(){
  if constexpr (RUN==0) return gA_dt; else if constexpr (RUN==1) return gB_dt0; else return gB_dt1; }
template<int RUN> __device__ __forceinline__ float* bufBC(){
  if constexpr (RUN==0) return gA_bc; else if constexpr (RUN==1) return gB_bc0; else return gB_bc1; }
template<int RUN> __device__ __forceinline__ float* bufY(){
  if constexpr (RUN==0) return gA_y; else if constexpr (RUN==1) return gB_y0; else return gB_y1; }
template<int RUN> __device__ __forceinline__ float* bufO(){
  if constexpr (RUN==0) return gA_o; else if constexpr (RUN==1) return gB_o0; else return gB_o1; }

__device__ __forceinline__ float warp_sum(float v){
  v += __shfl_xor_sync(0xffffffffu, v, 16);
  v += __shfl_xor_sync(0xffffffffu, v, 8);
  v += __shfl_xor_sync(0xffffffffu, v, 4);
  v += __shfl_xor_sync(0xffffffffu, v, 2);
  v += __shfl_xor_sync(0xffffffffu, v, 1);
  return v;
}

// ============ K1: gather + layernorm + in_proj ============
// 4 warps/block, each warp does 8 tokens of one sequence.
template<int RUN>
__global__ void __launch_bounds__(128) k_inproj(
    const float* __restrict__ x, const float* __restrict__ nw,
    const float* __restrict__ nb, const float* __restrict__ gt,
    const float* __restrict__ Win)
{
  constexpr int DM  = (RUN==0)?32:24;
  constexpr int DXZ = (RUN==0)?128:96;
  constexpr int LF  = (RUN==0)?LA:LB;
  constexpr int KO  = DXZ/32;
  __shared__ float Wt[DM*DXZ];                    // [d][o]
  __shared__ __align__(16) float vsh[4][DM][8];

  int tid = threadIdx.x;
  for (int i = tid; i < DXZ*DM; i += 128){
    int o = i / DM, d = i - o*DM;
    Wt[d*DXZ + o] = Win[i];
  }
  int w = tid >> 5, lane = tid & 31;
  int n = blockIdx.y, bh = n >> 3, bw = n & 7;
  int t0 = (blockIdx.x*4 + w)*8;

  float v[8];
  #pragma unroll
  for (int tok = 0; tok < 8; tok++){
    int t = t0 + tok; float val = 0.f;
    if (lane < DM && t < LF){
      if (t == 0) val = gt[lane];
      else {
        int q = t - 1, addr;
        if (RUN == 0){
          int row = q / 48, col = q - row*48;
          int i0 = row >> 1, r1 = row & 1, j0 = col >> 1, r2 = col & 1;
          addr = (lane*4 + r1*2 + r2)*36864 + (bh*24 + i0)*192 + bw*24 + j0;
        } else if (RUN == 1){
          int c = q / 24, j0 = q - c*24;
          addr = c*36864 + (bh*24 + lane)*192 + bw*24 + j0;
        } else {
          int c = q / 24, i0 = q - c*24;
          addr = c*36864 + (bh*24 + i0)*192 + bw*24 + lane;
        }
        val = __ldg(x + addr);
      }
    }
    v[tok] = val;
  }
  float nwv = (lane < DM) ? nw[lane] : 0.f;
  float nbv = (lane < DM) ? nb[lane] : 0.f;
  #pragma unroll
  for (int tok = 0; tok < 8; tok++){
    float s  = warp_sum(v[tok]);
    float s2 = warp_sum(v[tok]*v[tok]);
    float m  = s * (1.f/DM);
    float var = s2 * (1.f/DM) - m*m;
    float vn = (v[tok] - m) * rsqrtf(var + 1e-5f) * nwv + nbv;
    if (lane < DM) vsh[w][lane][tok] = vn;
  }
  __syncthreads();   // Wt + vsh ready

  float acc[KO][8];
  #pragma unroll
  for (int k = 0; k < KO; k++)
    #pragma unroll
    for (int j = 0; j < 8; j++) acc[k][j] = 0.f;

  #pragma unroll 4
  for (int d = 0; d < DM; d++){
    float4 v0 = ((const float4*)vsh[w][d])[0];
    float4 v1 = ((const float4*)vsh[w][d])[1];
    #pragma unroll
    for (int k = 0; k < KO; k++){
      float wv = Wt[d*DXZ + lane + 32*k];
      acc[k][0] = fmaf(wv, v0.x, acc[k][0]);
      acc[k][1] = fmaf(wv, v0.y, acc[k][1]);
      acc[k][2] = fmaf(wv, v0.z, acc[k][2]);
      acc[k][3] = fmaf(wv, v0.w, acc[k][3]);
      acc[k][4] = fmaf(wv, v1.x, acc[k][4]);
      acc[k][5] = fmaf(wv, v1.y, acc[k][5]);
      acc[k][6] = fmaf(wv, v1.z, acc[k][6]);
      acc[k][7] = fmaf(wv, v1.w, acc[k][7]);
    }
  }
  float* xz = bufXZ<RUN>();
  #pragma unroll
  for (int tok = 0; tok < 8; tok++){
    int t = t0 + tok;
    if (t < LF){
      float* op = xz + (n*LF + t)*DXZ + lane;
      #pragma unroll
      for (int k = 0; k < KO; k++) op[32*k] = acc[k][tok];
    }
  }
}

// ============ K2: depthwise conv + silu + x_proj + dt ============
// 4 warps/block, each warp does 4 tokens; lane covers channels lane, lane+32.
template<int RUN>
__global__ void __launch_bounds__(128) k_convxp(
  const float* __restrict__ convw, const float* __restrict__ convb,
  const float* __restrict__ Wx,    const float* __restrict__ dtw,
  const float* __restrict__ dtb)
{
  constexpr int DIN = (RUN==0)?64:48;
  constexpr int DXZ = (RUN==0)?128:96;
  constexpr int LF  = (RUN==0)?LA:LB;
  const float* xz = bufXZ<RUN>();
  float* xs_out = bufXS<RUN>();
  float* dt_out = bufDT<RUN>();
  float* bc_out = bufBC<RUN>();

  __shared__ float Wxt[DIN*34];                   // [d][o]
  __shared__ __align__(16) float vsh[4][DIN][4];
  int tid = threadIdx.x;
  for (int i = tid; i < 34*DIN; i += 128){
    int o = i / DIN, d = i - o*DIN;
    Wxt[d*34 + o] = Wx[i];
  }
  int w = tid >> 5, lane = tid & 31;
  int n = blockIdx.y;
  int t0 = (blockIdx.x*4 + w)*4;

  float cw[2][4], cb[2], w0c[2], w1c[2], db[2];
  #pragma unroll
  for (int kk = 0; kk < 2; kk++){
    int ch = lane + 32*kk;
    bool ok = ch < DIN;
    #pragma unroll
    for (int k = 0; k < 4; k++) cw[kk][k] = ok ? convw[ch*4+k] : 0.f;
    cb[kk]  = ok ? convb[ch]   : 0.f;
    w0c[kk] = ok ? dtw[ch*2+0] : 0.f;
    w1c[kk] = ok ? dtw[ch*2+1] : 0.f;
    db[kk]  = ok ? dtb[ch]     : 0.f;
  }
  float sv[2][4];
  #pragma unroll
  for (int tok = 0; tok < 4; tok++){
    int t = t0 + tok;
    bool valid = t < LF;
    #pragma unroll
    for (int kk = 0; kk < 2; kk++){
      int ch = lane + 32*kk;
      float a = cb[kk];
      if (valid && ch < DIN){
        #pragma unroll
        for (int k = 0; k < 4; k++){
          int ts = t + k - 3;
          if (ts >= 0) a = fmaf(xz[(n*LF + ts)*DXZ + ch], cw[kk][k], a);
        }
      }
      sv[kk][tok] = __fdividef(a, 1.f + __expf(-a));   // silu
    }
  }
  #pragma unroll
  for (int kk = 0; kk < 2; kk++){
    int ch = lane + 32*kk;
    if (ch < DIN){
      ((float4*)vsh[w][ch])[0] = make_float4(sv[kk][0],sv[kk][1],sv[kk][2],sv[kk][3]);
      #pragma unroll
      for (int tok = 0; tok < 4; tok++){
        int t = t0 + tok;
        if (t < LF) xs_out[(n*LF + t)*DIN + ch] = sv[kk][tok];
      }
    }
  }
  __syncthreads();   // Wxt + vsh ready

  float acc[4]  = {0,0,0,0};
  float acc2[4] = {0,0,0,0};
  #pragma unroll 8
  for (int d = 0; d < DIN; d++){
    float4 vv = ((const float4*)vsh[w][d])[0];
    float wv = Wxt[d*34 + lane];
    acc[0] = fmaf(wv, vv.x, acc[0]);
    acc[1] = fmaf(wv, vv.y, acc[1]);
    acc[2] = fmaf(wv, vv.z, acc[2]);
    acc[3] = fmaf(wv, vv.w, acc[3]);
    if (lane < 2){
      float w2 = Wxt[d*34 + 32 + lane];
      acc2[0] = fmaf(w2, vv.x, acc2[0]);
      acc2[1] = fmaf(w2, vv.y, acc2[1]);
      acc2[2] = fmaf(w2, vv.z, acc2[2]);
      acc2[3] = fmaf(w2, vv.w, acc2[3]);
    }
  }
  #pragma unroll
  for (int tok = 0; tok < 4; tok++){
    int t = t0 + tok;
    float d0 = __shfl_sync(0xffffffffu, acc[tok], 0);
    float d1 = __shfl_sync(0xffffffffu, acc[tok], 1);
    if (t < LF){
      #pragma unroll
      for (int kk = 0; kk < 2; kk++){
        int ch = lane + 32*kk;
        if (ch < DIN){
          float r  = fmaf(w0c[kk], d0, fmaf(w1c[kk], d1, db[kk]));
          float sp = fmaxf(r, 0.f) + __logf(1.f + __expf(-fabsf(r)));  // softplus
          dt_out[(n*LF + t)*DIN + ch] = sp;
        }
      }
      if (lane >= 2) bc_out[(n*LF + t)*32 + (lane-2)]  = acc[tok];
      else           bc_out[(n*LF + t)*32 + 30 + lane] = acc2[tok];
    }
  }
}

// ============ K3: selective scan (all 3 runs in one grid) ============
// 8 lanes per (seq,channel), 2 states/lane; 4 channels per warp.
__global__ void __launch_bounds__(256) k_scan(
  const float* __restrict__ alogA, const float* __restrict__ DA,
  const float* __restrict__ alogB, const float* __restrict__ DB)
{
  int wg = (blockIdx.x*256 + threadIdx.x) >> 5;      // 0..2559
  int lane = threadIdx.x & 31;
  int g = lane >> 3, sl = lane & 7;

  const float *dtp, *xsp, *zp, *bcp, *alog;
  float *yp; float Dd;
  int L, din, dxz;
  if (wg < 1024){
    int n = wg >> 4, d = ((wg & 15) << 2) + g;
    L = LA; din = 64; dxz = 128;
    dtp = gA_dt + (n*LA)*64 + d;
    xsp = gA_xs + (n*LA)*64 + d;
    zp  = gA_xz + (n*LA)*128 + 64 + d;
    bcp = gA_bc + (n*LA)*32;
    yp  = gA_y  + (n*(LA-1))*64 + d;
    alog = alogA + d*16; Dd = __ldg(DA + d);
  } else {
    int w2 = wg - 1024; int r1 = (w2 >= 768); if (r1) w2 -= 768;
    int n = w2 / 12, d = (w2 - n*12)*4 + g;
    L = LB; din = 48; dxz = 96;
    int base = (n*LB)*48 + d;
    if (!r1){
      dtp = gB_dt0 + base; xsp = gB_xs0 + base;
      zp  = gB_xz0 + (n*LB)*96 + 48 + d;
      bcp = gB_bc0 + (n*LB)*32;
      yp  = gB_y0  + (n*(LB-1))*48 + d;
    } else {
      dtp = gB_dt1 + base; xsp = gB_xs1 + base;
      zp  = gB_xz1 + (n*LB)*96 + 48 + d;
      bcp = gB_bc1 + (n*LB)*32;
      yp  = gB_y1  + (n*(LB-1))*48 + d;
    }
    alog = alogB + d*16; Dd = __ldg(DB + d);
  }
  float A0 = -expf(__ldg(alog + 2*sl));
  float A1 = -expf(__ldg(alog + 2*sl + 1));
  float h0 = 0.f, h1 = 0.f;
  for (int t = 0; t < L; t++){
    float dtv = __ldg(dtp); dtp += din;
    float u   = __ldg(xsp); xsp += din;
    float2 Bv = *(const float2*)(bcp + 2*sl);
    float2 Cv = *(const float2*)(bcp + 16 + 2*sl);
    bcp += 32;
    float a0 = __expf(dtv*A0);
    float a1 = __expf(dtv*A1);
    float du = dtv*u;
    h0 = fmaf(h0, a0, du*Bv.x);
    h1 = fmaf(h1, a1, du*Bv.y);
    float acc = fmaf(h1, Cv.y, h0*Cv.x);
    acc += __shfl_xor_sync(0xffffffffu, acc, 1);
    acc += __shfl_xor_sync(0xffffffffu, acc, 2);
    acc += __shfl_xor_sync(0xffffffffu, acc, 4);
    if (t > 0 && sl == 0){
      float zv = __ldg(zp + t*dxz);
      float sil = __fdividef(zv, 1.f + __expf(-zv));
      *yp = (acc + u*Dd) * sil;
      yp += din;
    }
  }
}

// ============ K4: out_proj ============
template<int RUN>
__global__ void __launch_bounds__(128) k_outproj(const float* __restrict__ Wo)
{
  constexpr int DIN = (RUN==0)?64:48;
  constexpr int DM  = (RUN==0)?32:24;
  constexpr int LT  = ((RUN==0)?LA:LB) - 1;
  const float* y = bufY<RUN>();
  float* o = bufO<RUN>();
  __shared__ float Wt[DIN*32];
  __shared__ __align__(16) float vsh[4][DIN][8];
  int tid = threadIdx.x;
  for (int i = tid; i < DIN*32; i += 128){
    int d = i >> 5, oo = i & 31;
    Wt[i] = (oo < DM) ? Wo[oo*DIN + d] : 0.f;
  }
  int w = tid >> 5, lane = tid & 31;
  int n = blockIdx.y;
  int t0 = (blockIdx.x*4 + w)*8;
  #pragma unroll
  for (int tok = 0; tok < 8; tok++){
    int t = t0 + tok; if (t > LT-1) t = LT-1;
    const float* ypt = y + (n*LT + t)*DIN;
    vsh[w][lane][tok] = ypt[lane];
    if (DIN > 32 && lane < DIN-32) vsh[w][32+lane][tok] = ypt[32+lane];
  }
  __syncthreads();
  float acc[8] = {0,0,0,0,0,0,0,0};
  #pragma unroll 4
  for (int d = 0; d < DIN; d++){
    float wv = Wt[d*32 + lane];
    float4 v0 = ((const float4*)vsh[w][d])[0];
    float4 v1 = ((const float4*)vsh[w][d])[1];
    acc[0] = fmaf(wv, v0.x, acc[0]);
    acc[1] = fmaf(wv, v0.y, acc[1]);
    acc[2] = fmaf(wv, v0.z, acc[2]);
    acc[3] = fmaf(wv, v0.w, acc[3]);
    acc[4] = fmaf(wv, v1.x, acc[4]);
    acc[5] = fmaf(wv, v1.y, acc[5]);
    acc[6] = fmaf(wv, v1.z, acc[6]);
    acc[7] = fmaf(wv, v1.w, acc[7]);
  }
  if (lane < DM){
    #pragma unroll
    for (int tok = 0; tok < 8; tok++){
      int t = t0 + tok;
      if (t < LT) o[(n*LT + t)*DM + lane] = acc[tok];
    }
  }
}

// ============ K5: combine into output ============
__global__ void __launch_bounds__(256) k_combine(float* __restrict__ out)
{
  int idx = blockIdx.x*256 + threadIdx.x;
  if (idx >= 128*192*192) return;
  int c = idx / 36864;
  int rem = idx - c*36864;
  int n = rem / 576;
  int rem2 = rem - n*576;
  int i = rem2 / 24;
  int j = rem2 - i*24;
  int d = c >> 2, r1 = (c >> 1) & 1, r2 = c & 1;
  float v0 = gA_o [(n*2304 + (2*i+r1)*48 + 2*j + r2)*32 + d];
  float v1 = gB_o0[(n*3072 + c*24 + j)*24 + i];
  float v2 = gB_o1[(n*3072 + c*24 + i)*24 + j];
  out[idx] = (v0 + v1 + v2) * (1.f/3.f);
}

// ============ host launch ============
extern "C" void kernel_launch(void* const* d_in, const int* in_sizes, int n_in,
                              void* d_out, int out_size) {
  (void)in_sizes; (void)n_in; (void)out_size;
  const float* X   = (const float*)d_in[0];
  const float* NW  = (const float*)d_in[1];
  const float* NB  = (const float*)d_in[2];
  const float* N2W = (const float*)d_in[3];
  const float* N2B = (const float*)d_in[4];
  const float* GT1 = (const float*)d_in[5];
  const float* GT2 = (const float*)d_in[6];
  const float* M1_IN  = (const float*)d_in[7];
  const float* M1_CW  = (const float*)d_in[8];
  const float* M1_CB  = (const float*)d_in[9];
  const float* M1_XW  = (const float*)d_in[10];
  const float* M1_DTW = (const float*)d_in[11];
  const float* M1_DTB = (const float*)d_in[12];
  const float* M1_AL  = (const float*)d_in[13];
  const float* M1_D   = (const float*)d_in[14];
  const float* M1_OW  = (const float*)d_in[15];
  const float* M2_IN  = (const float*)d_in[16];
  const float* M2_CW  = (const float*)d_in[17];
  const float* M2_CB  = (const float*)d_in[18];
  const float* M2_XW  = (const float*)d_in[19];
  const float* M2_DTW = (const float*)d_in[20];
  const float* M2_DTB = (const float*)d_in[21];
  const float* M2_AL  = (const float*)d_in[22];
  const float* M2_D   = (const float*)d_in[23];
  const float* M2_OW  = (const float*)d_in[24];

  k_inproj<0><<<dim3((LA+31)/32, 64), 128>>>(X, NW,  NB,  GT1, M1_IN);
  k_inproj<1><<<dim3((LB+31)/32, 64), 128>>>(X, N2W, N2B, GT2, M2_IN);
  k_inproj<2><<<dim3((LB+31)/32, 64), 128>>>(X, N2W, N2B, GT2, M2_IN);

  k_convxp<0><<<dim3((LA+15)/16, 64), 128>>>(M1_CW, M1_CB, M1_XW, M1_DTW, M1_DTB);
  k_convxp<1><<<dim3((LB+15)/16, 64), 128>>>(M2_CW, M2_CB, M2_XW, M2_DTW, M2_DTB);
  k_convxp<2><<<dim3((LB+15)/16, 64), 128>>>(M2_CW, M2_CB, M2_XW, M2_DTW, M2_DTB);

  k_scan<<<320, 256>>>(M1_AL, M1_D, M2_AL, M2_D);

  k_outproj<0><<<dim3(72, 64), 128>>>(M1_OW);
  k_outproj<1><<<dim3(96, 64), 128>>>(M2_OW);
  k_outproj<2><<<dim3(96, 64), 128>>>(M2_OW);

  k_combine<<<18432, 256>>>((float*)d_out);
}

// round 3
// speedup vs baseline: 2.3631x; 2.3631x over previous
#include <cuda_runtime.h>
#include <math.h>

#define NSEQ 64
static constexpr int LA  = 2305;   // run0 length (1 gt + 48*48)
static constexpr int LB  = 3073;   // run1/2 length (1 gt + 128*24)
static constexpr int LPA = 2308;   // padded strides (mult of 4)
static constexpr int LPB = 3076;

// ---------- scratch (device globals; allocation-free) ----------
__device__ __align__(16) float gA_xz [NSEQ*LA*128];
__device__ __align__(16) float gA_dtT[NSEQ*64*LPA];
__device__ __align__(16) float gA_xsT[NSEQ*64*LPA];
__device__ __align__(16) float gA_zsT[NSEQ*64*LPA];
__device__ __align__(16) float gA_bcT[NSEQ*32*LPA];
__device__ __align__(16) float gA_y  [NSEQ*(LA-1)*64];
__device__ __align__(16) float gA_o  [NSEQ*(LA-1)*32];

__device__ __align__(16) float gB_xz0 [NSEQ*LB*96];
__device__ __align__(16) float gB_dtT0[NSEQ*48*LPB];
__device__ __align__(16) float gB_xsT0[NSEQ*48*LPB];
__device__ __align__(16) float gB_zsT0[NSEQ*48*LPB];
__device__ __align__(16) float gB_bcT0[NSEQ*32*LPB];
__device__ __align__(16) float gB_y0  [NSEQ*(LB-1)*48];
__device__ __align__(16) float gB_o0  [NSEQ*(LB-1)*24];

__device__ __align__(16) float gB_xz1 [NSEQ*LB*96];
__device__ __align__(16) float gB_dtT1[NSEQ*48*LPB];
__device__ __align__(16) float gB_xsT1[NSEQ*48*LPB];
__device__ __align__(16) float gB_zsT1[NSEQ*48*LPB];
__device__ __align__(16) float gB_bcT1[NSEQ*32*LPB];
__device__ __align__(16) float gB_y1  [NSEQ*(LB-1)*48];
__device__ __align__(16) float gB_o1  [NSEQ*(LB-1)*24];

template<int RUN> __device__ __forceinline__ float* bufXZ(){
  if constexpr (RUN==0) return gA_xz; else if constexpr (RUN==1) return gB_xz0; else return gB_xz1; }
template<int RUN> __device__ __forceinline__ float* bufDTT(){
  if constexpr (RUN==0) return gA_dtT; else if constexpr (RUN==1) return gB_dtT0; else return gB_dtT1; }
template<int RUN> __device__ __forceinline__ float* bufXST(){
  if constexpr (RUN==0) return gA_xsT; else if constexpr (RUN==1) return gB_xsT0; else return gB_xsT1; }
template<int RUN> __device__ __forceinline__ float* bufZST(){
  if constexpr (RUN==0) return gA_zsT; else if constexpr (RUN==1) return gB_zsT0; else return gB_zsT1; }
template<int RUN> __device__ __forceinline__ float* bufBCT(){
  if constexpr (RUN==0) return gA_bcT; else if constexpr (RUN==1) return gB_bcT0; else return gB_bcT1; }
template<int RUN> __device__ __forceinline__ float* bufY(){
  if constexpr (RUN==0) return gA_y; else if constexpr (RUN==1) return gB_y0; else return gB_y1; }
template<int RUN> __device__ __forceinline__ float* bufO(){
  if constexpr (RUN==0) return gA_o; else if constexpr (RUN==1) return gB_o0; else return gB_o1; }

__device__ __forceinline__ float warp_sum(float v){
  v += __shfl_xor_sync(0xffffffffu, v, 16);
  v += __shfl_xor_sync(0xffffffffu, v, 8);
  v += __shfl_xor_sync(0xffffffffu, v, 4);
  v += __shfl_xor_sync(0xffffffffu, v, 2);
  v += __shfl_xor_sync(0xffffffffu, v, 1);
  return v;
}
__device__ __forceinline__ float silu_f(float x){
  return __fdividef(x, 1.f + __expf(-x));
}

// ============ K1: gather + layernorm + in_proj ============
template<int RUN>
__global__ void __launch_bounds__(128) k_inproj(
    const float* __restrict__ x, const float* __restrict__ nw,
    const float* __restrict__ nb, const float* __restrict__ gt,
    const float* __restrict__ Win)
{
  constexpr int DM  = (RUN==0)?32:24;
  constexpr int DXZ = (RUN==0)?128:96;
  constexpr int LF  = (RUN==0)?LA:LB;
  constexpr int KO  = DXZ/32;
  __shared__ float Wt[DM*DXZ];                    // [d][o]
  __shared__ __align__(16) float vsh[4][DM][8];

  int tid = threadIdx.x;
  for (int i = tid; i < DXZ*DM; i += 128){
    int o = i / DM, d = i - o*DM;
    Wt[d*DXZ + o] = Win[i];
  }
  int w = tid >> 5, lane = tid & 31;
  int n = blockIdx.y, bh = n >> 3, bw = n & 7;
  int t0 = (blockIdx.x*4 + w)*8;

  float v[8];
  #pragma unroll
  for (int tok = 0; tok < 8; tok++){
    int t = t0 + tok; float val = 0.f;
    if (lane < DM && t < LF){
      if (t == 0) val = gt[lane];
      else {
        int q = t - 1, addr;
        if (RUN == 0){
          int row = q / 48, col = q - row*48;
          int i0 = row >> 1, r1 = row & 1, j0 = col >> 1, r2 = col & 1;
          addr = (lane*4 + r1*2 + r2)*36864 + (bh*24 + i0)*192 + bw*24 + j0;
        } else if (RUN == 1){
          int c = q / 24, j0 = q - c*24;
          addr = c*36864 + (bh*24 + lane)*192 + bw*24 + j0;
        } else {
          int c = q / 24, i0 = q - c*24;
          addr = c*36864 + (bh*24 + i0)*192 + bw*24 + lane;
        }
        val = __ldg(x + addr);
      }
    }
    v[tok] = val;
  }
  float nwv = (lane < DM) ? nw[lane] : 0.f;
  float nbv = (lane < DM) ? nb[lane] : 0.f;
  #pragma unroll
  for (int tok = 0; tok < 8; tok++){
    float s  = warp_sum(v[tok]);
    float s2 = warp_sum(v[tok]*v[tok]);
    float m  = s * (1.f/DM);
    float var = s2 * (1.f/DM) - m*m;
    float vn = (v[tok] - m) * rsqrtf(var + 1e-5f) * nwv + nbv;
    if (lane < DM) vsh[w][lane][tok] = vn;
  }
  __syncthreads();

  float acc[KO][8];
  #pragma unroll
  for (int k = 0; k < KO; k++)
    #pragma unroll
    for (int j = 0; j < 8; j++) acc[k][j] = 0.f;

  #pragma unroll 4
  for (int d = 0; d < DM; d++){
    float4 v0 = ((const float4*)vsh[w][d])[0];
    float4 v1 = ((const float4*)vsh[w][d])[1];
    #pragma unroll
    for (int k = 0; k < KO; k++){
      float wv = Wt[d*DXZ + lane + 32*k];
      acc[k][0] = fmaf(wv, v0.x, acc[k][0]);
      acc[k][1] = fmaf(wv, v0.y, acc[k][1]);
      acc[k][2] = fmaf(wv, v0.z, acc[k][2]);
      acc[k][3] = fmaf(wv, v0.w, acc[k][3]);
      acc[k][4] = fmaf(wv, v1.x, acc[k][4]);
      acc[k][5] = fmaf(wv, v1.y, acc[k][5]);
      acc[k][6] = fmaf(wv, v1.z, acc[k][6]);
      acc[k][7] = fmaf(wv, v1.w, acc[k][7]);
    }
  }
  float* xz = bufXZ<RUN>();
  #pragma unroll
  for (int tok = 0; tok < 8; tok++){
    int t = t0 + tok;
    if (t < LF){
      float* op = xz + (n*LF + t)*DXZ + lane;
      #pragma unroll
      for (int k = 0; k < KO; k++) op[32*k] = acc[k][tok];
    }
  }
}

// ============ K2: conv + silu + x_proj + dt ; writes TRANSPOSED streams ============
template<int RUN>
__global__ void __launch_bounds__(128) k_convxp(
  const float* __restrict__ convw, const float* __restrict__ convb,
  const float* __restrict__ Wx,    const float* __restrict__ dtw,
  const float* __restrict__ dtb)
{
  constexpr int DIN = (RUN==0)?64:48;
  constexpr int DXZ = 2*DIN;
  constexpr int LF  = (RUN==0)?LA:LB;
  constexpr int LFP = (RUN==0)?LPA:LPB;
  const float* xz = bufXZ<RUN>();
  float* xsT = bufXST<RUN>();
  float* dtT = bufDTT<RUN>();
  float* zsT = bufZST<RUN>();
  float* bcT = bufBCT<RUN>();

  __shared__ float Wxt[DIN*34];                   // [d][o]
  __shared__ __align__(16) float vsh[4][DIN][4];
  int tid = threadIdx.x;
  for (int i = tid; i < 34*DIN; i += 128){
    int o = i / DIN, d = i - o*DIN;
    Wxt[d*34 + o] = Wx[i];
  }
  int w = tid >> 5, lane = tid & 31;
  int n = blockIdx.y;
  int t0 = (blockIdx.x*4 + w)*4;
  bool act = (t0 < LF);

  float cw[2][4], cb[2], w0c[2], w1c[2], db[2];
  #pragma unroll
  for (int kk = 0; kk < 2; kk++){
    int ch = lane + 32*kk;
    bool ok = ch < DIN;
    #pragma unroll
    for (int k = 0; k < 4; k++) cw[kk][k] = ok ? convw[ch*4+k] : 0.f;
    cb[kk]  = ok ? convb[ch]   : 0.f;
    w0c[kk] = ok ? dtw[ch*2+0] : 0.f;
    w1c[kk] = ok ? dtw[ch*2+1] : 0.f;
    db[kk]  = ok ? dtb[ch]     : 0.f;
  }
  float sv[2][4], zq[2][4];
  #pragma unroll
  for (int tok = 0; tok < 4; tok++){
    int t = t0 + tok;
    bool valid = t < LF;
    #pragma unroll
    for (int kk = 0; kk < 2; kk++){
      int ch = lane + 32*kk;
      float a = cb[kk];
      float zval = 0.f;
      if (valid && ch < DIN){
        #pragma unroll
        for (int k = 0; k < 4; k++){
          int ts = t + k - 3;
          if (ts >= 0) a = fmaf(xz[(n*LF + ts)*DXZ + ch], cw[kk][k], a);
        }
        zval = xz[(n*LF + t)*DXZ + DIN + ch];
      }
      sv[kk][tok] = silu_f(a);
      zq[kk][tok] = silu_f(zval);
    }
  }
  // transposed xs / zs stores + stage into smem for the GEMV
  #pragma unroll
  for (int kk = 0; kk < 2; kk++){
    int ch = lane + 32*kk;
    if (ch < DIN){
      ((float4*)vsh[w][ch])[0] = make_float4(sv[kk][0],sv[kk][1],sv[kk][2],sv[kk][3]);
      if (act){
        *(float4*)(xsT + (n*DIN+ch)*LFP + t0) = make_float4(sv[kk][0],sv[kk][1],sv[kk][2],sv[kk][3]);
        *(float4*)(zsT + (n*DIN+ch)*LFP + t0) = make_float4(zq[kk][0],zq[kk][1],zq[kk][2],zq[kk][3]);
      }
    }
  }
  __syncthreads();

  float acc[4]  = {0,0,0,0};
  float acc2[4] = {0,0,0,0};
  #pragma unroll 8
  for (int d = 0; d < DIN; d++){
    float4 vv = ((const float4*)vsh[w][d])[0];
    float wv = Wxt[d*34 + lane];
    acc[0] = fmaf(wv, vv.x, acc[0]);
    acc[1] = fmaf(wv, vv.y, acc[1]);
    acc[2] = fmaf(wv, vv.z, acc[2]);
    acc[3] = fmaf(wv, vv.w, acc[3]);
    if (lane < 2){
      float w2 = Wxt[d*34 + 32 + lane];
      acc2[0] = fmaf(w2, vv.x, acc2[0]);
      acc2[1] = fmaf(w2, vv.y, acc2[1]);
      acc2[2] = fmaf(w2, vv.z, acc2[2]);
      acc2[3] = fmaf(w2, vv.w, acc2[3]);
    }
  }
  // dt (softplus) per channel, transposed store
  float spv[2][4];
  #pragma unroll
  for (int tok = 0; tok < 4; tok++){
    float d0 = __shfl_sync(0xffffffffu, acc[tok], 0);
    float d1 = __shfl_sync(0xffffffffu, acc[tok], 1);
    #pragma unroll
    for (int kk = 0; kk < 2; kk++){
      float r = fmaf(w0c[kk], d0, fmaf(w1c[kk], d1, db[kk]));
      spv[kk][tok] = fmaxf(r, 0.f) + __logf(1.f + __expf(-fabsf(r)));
    }
  }
  if (act){
    #pragma unroll
    for (int kk = 0; kk < 2; kk++){
      int ch = lane + 32*kk;
      if (ch < DIN)
        *(float4*)(dtT + (n*DIN+ch)*LFP + t0) = make_float4(spv[kk][0],spv[kk][1],spv[kk][2],spv[kk][3]);
    }
    // B/C components (x_proj outputs 2..33) transposed: comp = o-2
    int comp = (lane >= 2) ? (lane - 2) : (30 + lane);
    float4 bv = (lane >= 2) ? make_float4(acc[0],acc[1],acc[2],acc[3])
                            : make_float4(acc2[0],acc2[1],acc2[2],acc2[3]);
    *(float4*)(bcT + (n*32+comp)*LFP + t0) = bv;
  }
}

// ============ K3: selective scan, streaming float4 loads ============
// 16 lanes per channel (1 state/lane), 2 channels per warp.
template<int L, int DIN, int LFP>
__device__ __forceinline__ void scan_seq(
  const float* __restrict__ dtT, const float* __restrict__ xsT,
  const float* __restrict__ zsT, const float* __restrict__ bcT,
  float* __restrict__ y, const float* __restrict__ alog,
  const float* __restrict__ Dv, int n, int ch2, int lane)
{
  int half = lane >> 4, s = lane & 15;
  int ch = ch2 + half;
  const float* dtp = dtT + (n*DIN + ch)*LFP;
  const float* xsp = xsT + (n*DIN + ch)*LFP;
  const float* zsp = zsT + (n*DIN + ch)*LFP;
  const float* Bp  = bcT + (n*32 + s)*LFP;
  const float* Cp  = bcT + (n*32 + 16 + s)*LFP;
  float A  = -expf(__ldg(alog + ch*16 + s));
  float Dd = __ldg(Dv + ch);
  float* yp = y + (size_t)n*(L-1)*DIN + ch;
  bool yl = (s == 0);
  float h = 0.f;
  constexpr int NB = (L-1)/4;   // 2304/3072 are multiples of 4
  for (int tb = 0; tb < NB; tb++){
    int t = tb*4;
    float4 dq = *(const float4*)(dtp + t);
    float4 uq = *(const float4*)(xsp + t);
    float4 Bq = __ldg((const float4*)(Bp + t));
    float4 Cq = __ldg((const float4*)(Cp + t));
    float4 zv = make_float4(0,0,0,0);
    if (yl) zv = *(const float4*)(zsp + t);
    float da[4] = {dq.x,dq.y,dq.z,dq.w};
    float ua[4] = {uq.x,uq.y,uq.z,uq.w};
    float Ba[4] = {Bq.x,Bq.y,Bq.z,Bq.w};
    float Ca[4] = {Cq.x,Cq.y,Cq.z,Cq.w};
    float za[4] = {zv.x,zv.y,zv.z,zv.w};
    #pragma unroll
    for (int j = 0; j < 4; j++){
      float a = __expf(da[j]*A);
      h = fmaf(h, a, da[j]*ua[j]*Ba[j]);
      float acc = h * Ca[j];
      acc += __shfl_xor_sync(0xffffffffu, acc, 1);
      acc += __shfl_xor_sync(0xffffffffu, acc, 2);
      acc += __shfl_xor_sync(0xffffffffu, acc, 4);
      acc += __shfl_xor_sync(0xffffffffu, acc, 8);
      if (yl && (t + j > 0))
        yp[(t+j-1)*DIN] = fmaf(ua[j], Dd, acc) * za[j];
    }
  }
  { // tail: t = L-1
    int t = L-1;
    float dtv = dtp[t], u = xsp[t];
    float Bv = __ldg(Bp + t), Cv = __ldg(Cp + t);
    float a = __expf(dtv*A);
    h = fmaf(h, a, dtv*u*Bv);
    float acc = h * Cv;
    acc += __shfl_xor_sync(0xffffffffu, acc, 1);
    acc += __shfl_xor_sync(0xffffffffu, acc, 2);
    acc += __shfl_xor_sync(0xffffffffu, acc, 4);
    acc += __shfl_xor_sync(0xffffffffu, acc, 8);
    if (yl) yp[(t-1)*DIN] = fmaf(u, Dd, acc) * zsp[t];
  }
}

__global__ void __launch_bounds__(256) k_scan(
  const float* __restrict__ alogA, const float* __restrict__ DA,
  const float* __restrict__ alogB, const float* __restrict__ DB)
{
  int wg = (blockIdx.x*256 + threadIdx.x) >> 5;   // 0..5119
  int lane = threadIdx.x & 31;
  if (wg < 2048){
    int n = wg >> 5, ch2 = (wg & 31)*2;           // 32 warps/seq (64 ch)
    scan_seq<LA,64,LPA>(gA_dtT, gA_xsT, gA_zsT, gA_bcT, gA_y, alogA, DA, n, ch2, lane);
  } else {
    int w2 = wg - 2048;                           // 0..3071
    if (w2 < 1536){
      int n = w2/24, ch2 = (w2 - n*24)*2;         // 24 warps/seq (48 ch)
      scan_seq<LB,48,LPB>(gB_dtT0, gB_xsT0, gB_zsT0, gB_bcT0, gB_y0, alogB, DB, n, ch2, lane);
    } else {
      w2 -= 1536;
      int n = w2/24, ch2 = (w2 - n*24)*2;
      scan_seq<LB,48,LPB>(gB_dtT1, gB_xsT1, gB_zsT1, gB_bcT1, gB_y1, alogB, DB, n, ch2, lane);
    }
  }
}

// ============ K4: out_proj ============
template<int RUN>
__global__ void __launch_bounds__(128) k_outproj(const float* __restrict__ Wo)
{
  constexpr int DIN = (RUN==0)?64:48;
  constexpr int DM  = (RUN==0)?32:24;
  constexpr int LT  = ((RUN==0)?LA:LB) - 1;
  const float* y = bufY<RUN>();
  float* o = bufO<RUN>();
  __shared__ float Wt[DIN*32];
  __shared__ __align__(16) float vsh[4][DIN][8];
  int tid = threadIdx.x;
  for (int i = tid; i < DIN*32; i += 128){
    int d = i >> 5, oo = i & 31;
    Wt[i] = (oo < DM) ? Wo[oo*DIN + d] : 0.f;
  }
  int w = tid >> 5, lane = tid & 31;
  int n = blockIdx.y;
  int t0 = (blockIdx.x*4 + w)*8;
  #pragma unroll
  for (int tok = 0; tok < 8; tok++){
    int t = t0 + tok; if (t > LT-1) t = LT-1;
    const float* ypt = y + (n*LT + t)*DIN;
    vsh[w][lane][tok] = ypt[lane];
    if (DIN > 32 && lane < DIN-32) vsh[w][32+lane][tok] = ypt[32+lane];
  }
  __syncthreads();
  float acc[8] = {0,0,0,0,0,0,0,0};
  #pragma unroll 4
  for (int d = 0; d < DIN; d++){
    float wv = Wt[d*32 + lane];
    float4 v0 = ((const float4*)vsh[w][d])[0];
    float4 v1 = ((const float4*)vsh[w][d])[1];
    acc[0] = fmaf(wv, v0.x, acc[0]);
    acc[1] = fmaf(wv, v0.y, acc[1]);
    acc[2] = fmaf(wv, v0.z, acc[2]);
    acc[3] = fmaf(wv, v0.w, acc[3]);
    acc[4] = fmaf(wv, v1.x, acc[4]);
    acc[5] = fmaf(wv, v1.y, acc[5]);
    acc[6] = fmaf(wv, v1.z, acc[6]);
    acc[7] = fmaf(wv, v1.w, acc[7]);
  }
  if (lane < DM){
    #pragma unroll
    for (int tok = 0; tok < 8; tok++){
      int t = t0 + tok;
      if (t < LT) o[(n*LT + t)*DM + lane] = acc[tok];
    }
  }
}

// ============ K5: combine into output ============
__global__ void __launch_bounds__(256) k_combine(float* __restrict__ out)
{
  int idx = blockIdx.x*256 + threadIdx.x;
  if (idx >= 128*192*192) return;
  int c = idx / 36864;
  int rem = idx - c*36864;
  int n = rem / 576;
  int rem2 = rem - n*576;
  int i = rem2 / 24;
  int j = rem2 - i*24;
  int d = c >> 2, r1 = (c >> 1) & 1, r2 = c & 1;
  float v0 = gA_o [(n*2304 + (2*i+r1)*48 + 2*j + r2)*32 + d];
  float v1 = gB_o0[(n*3072 + c*24 + j)*24 + i];
  float v2 = gB_o1[(n*3072 + c*24 + i)*24 + j];
  out[idx] = (v0 + v1 + v2) * (1.f/3.f);
}

// ============ host launch ============
extern "C" void kernel_launch(void* const* d_in, const int* in_sizes, int n_in,
                              void* d_out, int out_size) {
  (void)in_sizes; (void)n_in; (void)out_size;
  const float* X   = (const float*)d_in[0];
  const float* NW  = (const float*)d_in[1];
  const float* NB  = (const float*)d_in[2];
  const float* N2W = (const float*)d_in[3];
  const float* N2B = (const float*)d_in[4];
  const float* GT1 = (const float*)d_in[5];
  const float* GT2 = (const float*)d_in[6];
  const float* M1_IN  = (const float*)d_in[7];
  const float* M1_CW  = (const float*)d_in[8];
  const float* M1_CB  = (const float*)d_in[9];
  const float* M1_XW  = (const float*)d_in[10];
  const float* M1_DTW = (const float*)d_in[11];
  const float* M1_DTB = (const float*)d_in[12];
  const float* M1_AL  = (const float*)d_in[13];
  const float* M1_D   = (const float*)d_in[14];
  const float* M1_OW  = (const float*)d_in[15];
  const float* M2_IN  = (const float*)d_in[16];
  const float* M2_CW  = (const float*)d_in[17];
  const float* M2_CB  = (const float*)d_in[18];
  const float* M2_XW  = (const float*)d_in[19];
  const float* M2_DTW = (const float*)d_in[20];
  const float* M2_DTB = (const float*)d_in[21];
  const float* M2_AL  = (const float*)d_in[22];
  const float* M2_D   = (const float*)d_in[23];
  const float* M2_OW  = (const float*)d_in[24];

  k_inproj<0><<<dim3((LA+31)/32, 64), 128>>>(X, NW,  NB,  GT1, M1_IN);
  k_inproj<1><<<dim3((LB+31)/32, 64), 128>>>(X, N2W, N2B, GT2, M2_IN);
  k_inproj<2><<<dim3((LB+31)/32, 64), 128>>>(X, N2W, N2B, GT2, M2_IN);

  k_convxp<0><<<dim3((LA+15)/16, 64), 128>>>(M1_CW, M1_CB, M1_XW, M1_DTW, M1_DTB);
  k_convxp<1><<<dim3((LB+15)/16, 64), 128>>>(M2_CW, M2_CB, M2_XW, M2_DTW, M2_DTB);
  k_convxp<2><<<dim3((LB+15)/16, 64), 128>>>(M2_CW, M2_CB, M2_XW, M2_DTW, M2_DTB);

  k_scan<<<640, 256>>>(M1_AL, M1_D, M2_AL, M2_D);

  k_outproj<0><<<dim3(72, 64), 128>>>(M1_OW);
  k_outproj<1><<<dim3(96, 64), 128>>>(M2_OW);
  k_outproj<2><<<dim3(96, 64), 128>>>(M2_OW);

  k_combine<<<18432, 256>>>((float*)d_out);
}